// round 1
// baseline (speedup 1.0000x reference)
#include <cuda_runtime.h>
#include <math.h>

// Problem constants
#define Bb   128
#define Tt   64
#define Ff   2048
#define Hh   2048
#define Cc   22
#define Dd   8
#define Rr   (Bb*Tt)      // 8192 parallel decoder rows
#define G4f  (4*Ff)       // 8192
#define G4h  (4*Hh)       // 8192

// ---------------- scratch (device globals; no allocation allowed) ----------
static __device__ float g_dec_h[(size_t)Rr * Ff];     // 64 MB
static __device__ float g_dec_c[(size_t)Rr * Ff];     // 64 MB
static __device__ float g_gates[(size_t)Rr * G4f];    // 256 MB
static __device__ float g_fut  [(size_t)Rr * Cc];
static __device__ float g_P    [(size_t)Rr * G4h];    // 256 MB (precomputed enc input gates)
static __device__ float g_egates[(size_t)Bb * G4h];
static __device__ float g_eh   [(size_t)Bb * Hh];
static __device__ float g_ec   [(size_t)Bb * Hh];
static __device__ float g_dec_bias[G4f];
static __device__ float g_enc_bias[G4h];

// ---------------- generic NT GEMM: C[M,N] = A[M,K]*B[N,K]^T (+A2*B2^T) (+bias[n]) (+Cin)
#define BM 128
#define BN 128
#define BK 16

__global__ __launch_bounds__(256, 2)
void gemm_nt(const float* __restrict__ A,  int lda,
             const float* __restrict__ Bm, int ldb, int K,
             const float* __restrict__ A2, int lda2,
             const float* __restrict__ B2, int ldb2, int K2,
             float* __restrict__ C, long long ldc,
             const float* __restrict__ bias,
             const float* __restrict__ Cin, long long ldcin,
             int M, int N)
{
    __shared__ float As[BK][BM + 1];
    __shared__ float Bs[BK][BN + 1];

    const int bm = blockIdx.y * BM;
    const int bn = blockIdx.x * BN;
    const int tid = threadIdx.x;
    const int tx = tid & 15;   // n group
    const int ty = tid >> 4;   // m group

    float acc[8][8];
#pragma unroll
    for (int i = 0; i < 8; i++)
#pragma unroll
        for (int j = 0; j < 8; j++) acc[i][j] = 0.f;

    for (int ph = 0; ph < 2; ph++) {
        const float* Ap  = ph ? A2   : A;
        const float* Bp  = ph ? B2   : Bm;
        const int ldap   = ph ? lda2 : lda;
        const int ldbp   = ph ? ldb2 : ldb;
        const int Kp     = ph ? K2   : K;
        if (Ap == nullptr || Kp <= 0) continue;

        for (int k0 = 0; k0 < Kp; k0 += BK) {
#pragma unroll
            for (int e = tid; e < BM * BK; e += 256) {
                int row = e >> 4, col = e & 15;
                int m = bm + row, k = k0 + col;
                As[col][row] = (m < M && k < Kp) ? Ap[(long long)m * ldap + k] : 0.f;
            }
#pragma unroll
            for (int e = tid; e < BN * BK; e += 256) {
                int row = e >> 4, col = e & 15;
                int n = bn + row, k = k0 + col;
                Bs[col][row] = (n < N && k < Kp) ? Bp[(long long)n * ldbp + k] : 0.f;
            }
            __syncthreads();
#pragma unroll
            for (int kk = 0; kk < BK; kk++) {
                float a[8], b[8];
#pragma unroll
                for (int i = 0; i < 8; i++) a[i] = As[kk][ty + i * 16];
#pragma unroll
                for (int j = 0; j < 8; j++) b[j] = Bs[kk][tx + j * 16];
#pragma unroll
                for (int i = 0; i < 8; i++)
#pragma unroll
                    for (int j = 0; j < 8; j++)
                        acc[i][j] += a[i] * b[j];
            }
            __syncthreads();
        }
    }

#pragma unroll
    for (int i = 0; i < 8; i++) {
        int m = bm + ty + i * 16;
        if (m >= M) continue;
#pragma unroll
        for (int j = 0; j < 8; j++) {
            int n = bn + tx + j * 16;
            if (n >= N) continue;
            float v = acc[i][j];
            if (bias) v += bias[n];
            if (Cin)  v += Cin[(long long)m * ldcin + n];
            C[(long long)m * ldc + n] = v;
        }
    }
}

// ---------------- skinny NT GEMM (warp per output element), K % 4 == 0 ----
__global__ void skinny_nt(const float* __restrict__ A, long long lda,
                          const float* __restrict__ Bm, long long ldb, int K,
                          float* __restrict__ C, long long ldc,
                          const float* __restrict__ bias, int M, int N)
{
    int w    = (int)((blockIdx.x * (long long)blockDim.x + threadIdx.x) >> 5);
    int lane = threadIdx.x & 31;
    if (w >= M * N) return;
    int m = w / N, n = w - m * N;
    const float* a = A  + (long long)m * lda;
    const float* b = Bm + (long long)n * ldb;
    float s = 0.f;
    for (int k = lane * 4; k < K; k += 128) {
        float4 av = *reinterpret_cast<const float4*>(a + k);
        float4 bv = *reinterpret_cast<const float4*>(b + k);
        s += av.x * bv.x + av.y * bv.y + av.z * bv.z + av.w * bv.w;
    }
#pragma unroll
    for (int off = 16; off; off >>= 1) s += __shfl_down_sync(0xffffffffu, s, off);
    if (lane == 0) C[(long long)m * ldc + n] = s + (bias ? bias[n] : 0.f);
}

// ---------------- pointwise LSTM cell (gate order i,f,g,o) -----------------
__device__ __forceinline__ float sigm(float x) { return 1.f / (1.f + __expf(-x)); }

__global__ void lstm_pointwise(const float* __restrict__ gates, long long ldg,
                               float* __restrict__ h, float* __restrict__ c,
                               int rows, int nh)
{
    long long total = (long long)rows * nh;
    for (long long idx = blockIdx.x * (long long)blockDim.x + threadIdx.x;
         idx < total; idx += (long long)gridDim.x * blockDim.x) {
        int r = (int)(idx / nh);
        int j = (int)(idx - (long long)r * nh);
        const float* gr = gates + (long long)r * ldg;
        float ig = sigm(gr[j]);
        float fg = sigm(gr[j + nh]);
        float gg = tanhf(gr[j + 2 * nh]);
        float og = sigm(gr[j + 3 * nh]);
        float cn = fg * c[idx] + ig * gg;
        c[idx] = cn;
        h[idx] = og * tanhf(cn);
    }
}

// ---------------- small helpers -------------------------------------------
__global__ void vec_add2(const float* __restrict__ a, const float* __restrict__ b,
                         float* __restrict__ o, int n)
{
    int i = blockIdx.x * blockDim.x + threadIdx.x;
    if (i < n) o[i] = a[i] + b[i];
}

// dec_scores layout: [B, T, D, C]; fut rows are r = b*T + t
__global__ void scatter_fut(const float* __restrict__ fut, float* __restrict__ outdec, int d)
{
    int idx = blockIdx.x * blockDim.x + threadIdx.x;
    if (idx >= Rr * Cc) return;
    int r = idx / Cc, c = idx - r * Cc;
    outdec[((long long)r * Dd + d) * Cc + c] = fut[idx];
}

// ---------------- launch ----------------------------------------------------
extern "C" void kernel_launch(void* const* d_in, const int* in_sizes, int n_in,
                              void* d_out, int out_size)
{
    const float* x       = (const float*)d_in[0];   // [B, T, F]  -> rows r=b*T+t are [R,F]
    const float* dec_Wih = (const float*)d_in[1];   // [4F, C]
    const float* dec_Whh = (const float*)d_in[2];   // [4F, F]
    const float* dec_bih = (const float*)d_in[3];
    const float* dec_bhh = (const float*)d_in[4];
    const float* tr_W    = (const float*)d_in[5];   // [C, F]
    const float* tr_b    = (const float*)d_in[6];
    const float* enc_Wih = (const float*)d_in[7];   // [4H, F+C]
    const float* enc_Whh = (const float*)d_in[8];   // [4H, H]
    const float* enc_bih = (const float*)d_in[9];
    const float* enc_bhh = (const float*)d_in[10];
    const float* cls_W   = (const float*)d_in[11];  // [C, H]
    const float* cls_b   = (const float*)d_in[12];

    float* out     = (float*)d_out;                     // enc_scores [B,T,C]
    float* out_dec = out + (size_t)Bb * Tt * Cc;        // dec_scores [B,T,D,C]

    float *dec_h, *dec_c, *gates, *fut, *P, *egates, *eh, *ec, *dbias, *ebias;
    cudaGetSymbolAddress((void**)&dec_h,  g_dec_h);
    cudaGetSymbolAddress((void**)&dec_c,  g_dec_c);
    cudaGetSymbolAddress((void**)&gates,  g_gates);
    cudaGetSymbolAddress((void**)&fut,    g_fut);
    cudaGetSymbolAddress((void**)&P,      g_P);
    cudaGetSymbolAddress((void**)&egates, g_egates);
    cudaGetSymbolAddress((void**)&eh,     g_eh);
    cudaGetSymbolAddress((void**)&ec,     g_ec);
    cudaGetSymbolAddress((void**)&dbias,  g_dec_bias);
    cudaGetSymbolAddress((void**)&ebias,  g_enc_bias);

    // init (re-done every replay; graph-capturable ops only)
    cudaMemcpyAsync(dec_h, x, sizeof(float) * (size_t)Rr * Ff, cudaMemcpyDeviceToDevice, 0);
    cudaMemsetAsync(dec_c, 0, sizeof(float) * (size_t)Rr * Ff, 0);
    cudaMemsetAsync(fut,   0, sizeof(float) * (size_t)Rr * Cc, 0);
    cudaMemsetAsync(eh,    0, sizeof(float) * (size_t)Bb * Hh, 0);
    cudaMemsetAsync(ec,    0, sizeof(float) * (size_t)Bb * Hh, 0);
    vec_add2<<<(G4f + 255) / 256, 256>>>(dec_bih, dec_bhh, dbias, G4f);
    vec_add2<<<(G4h + 255) / 256, 256>>>(enc_bih, enc_bhh, ebias, G4h);

    dim3 blk(256);

    // ---- Phase 1: all 64 decoder loops batched (rows r = b*T+t), 8 steps ----
    for (int d = 0; d < Dd; d++) {
        dim3 grid(G4f / BN, Rr / BM); // (64,64)
        // gates = h @ Whh^T + fut @ Wih^T + (bih+bhh)
        gemm_nt<<<grid, blk>>>(dec_h, Ff, dec_Whh, Ff, Ff,
                               fut, Cc, dec_Wih, Cc, Cc,
                               gates, (long long)G4f, dbias,
                               nullptr, 0, Rr, G4f);
        long long tot = (long long)Rr * Ff;
        lstm_pointwise<<<(unsigned)((tot + 255) / 256), 256>>>(gates, G4f, dec_h, dec_c, Rr, Ff);
        // fut = h @ tr_W^T + tr_b   (warp-per-output)
        long long warps = (long long)Rr * Cc;
        skinny_nt<<<(unsigned)((warps * 32 + 255) / 256), 256>>>(dec_h, Ff, tr_W, Ff, Ff,
                                                                 fut, Cc, tr_b, Rr, Cc);
        scatter_fut<<<(Rr * Cc + 255) / 256, 256>>>(fut, out_dec, d);
    }

    // ---- Phase 2: P[r,:] = [x_t, fut_final] @ enc_Wih^T + (bih+bhh), all t at once ----
    {
        dim3 grid(G4h / BN, Rr / BM);
        gemm_nt<<<grid, blk>>>(x, Ff, enc_Wih, Ff + Cc, Ff,
                               fut, Cc, enc_Wih + Ff, Ff + Cc, Cc,
                               P, (long long)G4h, ebias,
                               nullptr, 0, Rr, G4h);
    }

    // ---- Phase 3: sequential encoder recurrence over t ----
    for (int t = 0; t < Tt; t++) {
        dim3 grid(G4h / BN, (Bb + BM - 1) / BM); // (64,1)
        // egates = eh @ enc_Whh^T + P[rows b*T+t]
        gemm_nt<<<grid, blk>>>(eh, Hh, enc_Whh, Hh, Hh,
                               nullptr, 0, nullptr, 0, 0,
                               egates, (long long)G4h, nullptr,
                               P + (long long)t * G4h, (long long)Tt * G4h,
                               Bb, G4h);
        long long tot = (long long)Bb * Hh;
        lstm_pointwise<<<(unsigned)((tot + 255) / 256), 256>>>(egates, G4h, eh, ec, Bb, Hh);
        // enc_scores[:, t, :] = eh @ cls_W^T + cls_b
        long long warps = (long long)Bb * Cc;
        skinny_nt<<<(unsigned)((warps * 32 + 255) / 256), 256>>>(eh, Hh, cls_W, Hh, Hh,
                                                                 out + (long long)t * Cc,
                                                                 (long long)Tt * Cc, cls_b,
                                                                 Bb, Cc);
    }
}

// round 3
// speedup vs baseline: 2.6661x; 2.6661x over previous
#include <cuda_runtime.h>
#include <cuda_bf16.h>
#include <cstdint>
#include <stdint.h>
#include <math.h>

// Problem constants
#define Bb   128
#define Tt   64
#define Ff   2048
#define Hh   2048
#define Cc   22
#define Dd   8
#define Rr   (Bb*Tt)      // 8192
#define G4f  (4*Ff)       // 8192
#define G4h  (4*Hh)       // 8192

// ---------------- scratch (device globals) ---------------------------------
static __device__ float g_dec_h[(size_t)Rr * Ff];
static __device__ float g_dec_c[(size_t)Rr * Ff];
static __device__ float g_gates[(size_t)Rr * G4f];      // 256 MB
static __device__ float g_P    [(size_t)Rr * G4h];      // 256 MB
static __device__ float g_fut  [(size_t)Rr * Cc];
static __device__ float g_egates[(size_t)Bb * G4h];
static __device__ float g_eh   [(size_t)Bb * Hh];
static __device__ float g_ec   [(size_t)Bb * Hh];
static __device__ float g_dbias[G4f];
static __device__ float g_ebias[G4h];
static __device__ float g_Wt_dec[Cc * G4f];             // dec_Wih transposed [22,8192]
static __device__ float g_Wt_enc[Cc * G4h];             // enc_Wih cols 2048..2069 transposed

static __device__ __nv_bfloat16 g_h_hi [(size_t)Rr * Ff],  g_h_lo [(size_t)Rr * Ff];
static __device__ __nv_bfloat16 g_x_hi [(size_t)Rr * Ff],  g_x_lo [(size_t)Rr * Ff];
static __device__ __nv_bfloat16 g_eh_hi[(size_t)Bb * Hh],  g_eh_lo[(size_t)Bb * Hh];
static __device__ __nv_bfloat16 g_Wdec_hi[(size_t)G4f * Ff], g_Wdec_lo[(size_t)G4f * Ff];
static __device__ __nv_bfloat16 g_Wih_hi [(size_t)G4h * Ff], g_Wih_lo [(size_t)G4h * Ff];
static __device__ __nv_bfloat16 g_Whh_hi [(size_t)G4h * Hh], g_Whh_lo [(size_t)G4h * Hh];

// ---------------- PTX helpers ----------------------------------------------
__device__ __forceinline__ void mma_bf16(float* c,
                                         unsigned a0, unsigned a1, unsigned a2, unsigned a3,
                                         unsigned b0, unsigned b1)
{
    asm volatile(
        "mma.sync.aligned.m16n8k16.row.col.f32.bf16.bf16.f32 "
        "{%0,%1,%2,%3}, {%4,%5,%6,%7}, {%8,%9}, {%0,%1,%2,%3};\n"
        : "+f"(c[0]), "+f"(c[1]), "+f"(c[2]), "+f"(c[3])
        : "r"(a0), "r"(a1), "r"(a2), "r"(a3), "r"(b0), "r"(b1));
}
__device__ __forceinline__ void ldsm4(unsigned* r, unsigned addr)
{
    asm volatile("ldmatrix.sync.aligned.m8n8.x4.shared.b16 {%0,%1,%2,%3}, [%4];\n"
                 : "=r"(r[0]), "=r"(r[1]), "=r"(r[2]), "=r"(r[3]) : "r"(addr));
}
__device__ __forceinline__ void ldsm2(unsigned* r, unsigned addr)
{
    asm volatile("ldmatrix.sync.aligned.m8n8.x2.shared.b16 {%0,%1}, [%2];\n"
                 : "=r"(r[0]), "=r"(r[1]) : "r"(addr));
}
__device__ __forceinline__ void cp16(unsigned saddr, const void* g)
{
    asm volatile("cp.async.cg.shared.global [%0], [%1], 16;\n" :: "r"(saddr), "l"(g));
}

// ---------------- bf16x3 tensor-core GEMM ----------------------------------
// C[M,N] = (Ahi+Alo)[M,K] * (Bhi+Blo)[N,K]^T (+ Cin)   [drops lo*lo term]
// M % 128 == 0, N % 128 == 0, K % 32 == 0.  256 threads, warp tile 64x32.
#define GBM 128
#define GBN 128
#define GBK 32
#define SLD 40                         // 32 + 8 pad (bf16 elems)
#define TILE_E (GBM * SLD)             // elems per tile
#define STAGE_E (4 * TILE_E)           // Ahi,Alo,Bhi,Blo
#define OFF_AL (TILE_E * 2)            // byte offsets within stage
#define OFF_BH (2 * TILE_E * 2)
#define OFF_BL (3 * TILE_E * 2)
#define STAGE_B (STAGE_E * 2)

extern __shared__ __nv_bfloat16 smem_[];

__global__ void __launch_bounds__(256, 1)
gemm_bf16x3(const __nv_bfloat16* __restrict__ Ah, const __nv_bfloat16* __restrict__ Al, int lda,
            const __nv_bfloat16* __restrict__ Bh, const __nv_bfloat16* __restrict__ Bl, int ldb,
            int K,
            float* __restrict__ C, long long ldc,
            const float* __restrict__ Cin, long long ldcin,
            int M, int N)
{
    const int bm = blockIdx.y * GBM;
    const int bn = blockIdx.x * GBN;
    const int tid = threadIdx.x;
    const int warp = tid >> 5;
    const int lane = tid & 31;
    const int wm = (warp >> 2) * 64;   // 0 or 64
    const int wn = (warp & 3) * 32;    // 0,32,64,96

    const unsigned sbase = (unsigned)__cvta_generic_to_shared(smem_);

    float acc[4][4][4];
#pragma unroll
    for (int i = 0; i < 4; i++)
#pragma unroll
        for (int j = 0; j < 4; j++)
#pragma unroll
            for (int e = 0; e < 4; e++) acc[i][j][e] = 0.f;

    const int iters = K / GBK;

    // ---- stage loader ----
    auto load_stage = [&](int st, int k0) {
        unsigned so = sbase + st * STAGE_B;
#pragma unroll
        for (int a = 0; a < 2; ++a) {
            int ch = tid + a * 256;            // 0..511
            int row = ch >> 2;
            int kc = (ch & 3) * 8;             // bf16 elems
            unsigned sa = so + (unsigned)(row * SLD + kc) * 2;
            const __nv_bfloat16* ga = Ah + (size_t)(bm + row) * lda + k0 + kc;
            const __nv_bfloat16* gl = Al + (size_t)(bm + row) * lda + k0 + kc;
            const __nv_bfloat16* gb = Bh + (size_t)(bn + row) * ldb + k0 + kc;
            const __nv_bfloat16* gc = Bl + (size_t)(bn + row) * ldb + k0 + kc;
            cp16(sa, ga);
            cp16(sa + OFF_AL, gl);
            cp16(sa + OFF_BH, gb);
            cp16(sa + OFF_BL, gc);
        }
        asm volatile("cp.async.commit_group;\n");
    };

    load_stage(0, 0);

    for (int it = 0; it < iters; ++it) {
        if (it + 1 < iters) {
            load_stage((it + 1) & 1, (it + 1) * GBK);
            asm volatile("cp.async.wait_group 1;\n");
        } else {
            asm volatile("cp.async.wait_group 0;\n");
        }
        __syncthreads();

        unsigned so = sbase + (it & 1) * STAGE_B;
#pragma unroll
        for (int ks = 0; ks < 2; ++ks) {
            unsigned ah[4][4], al[4][4], bh[4][2], bl[4][2];
            const int kb = ks * 16;
            const int arow = wm + (lane & 15);
            const int akb  = kb + ((lane & 16) ? 8 : 0);
#pragma unroll
            for (int mf = 0; mf < 4; ++mf) {
                unsigned ad = so + (unsigned)((arow + mf * 16) * SLD + akb) * 2;
                ldsm4(ah[mf], ad);
                ldsm4(al[mf], ad + OFF_AL);
            }
            const int brow = wn + (lane & 7);
            const int bkb  = kb + ((lane & 8) ? 8 : 0);
#pragma unroll
            for (int nf = 0; nf < 4; ++nf) {
                unsigned bd = so + OFF_BH + (unsigned)((brow + nf * 8) * SLD + bkb) * 2;
                ldsm2(bh[nf], bd);
                ldsm2(bl[nf], bd + (OFF_BL - OFF_BH));
            }
#pragma unroll
            for (int mf = 0; mf < 4; ++mf)
#pragma unroll
                for (int nf = 0; nf < 4; ++nf) {
                    mma_bf16(acc[mf][nf], ah[mf][0], ah[mf][1], ah[mf][2], ah[mf][3],
                             bh[nf][0], bh[nf][1]);
                    mma_bf16(acc[mf][nf], ah[mf][0], ah[mf][1], ah[mf][2], ah[mf][3],
                             bl[nf][0], bl[nf][1]);
                    mma_bf16(acc[mf][nf], al[mf][0], al[mf][1], al[mf][2], al[mf][3],
                             bh[nf][0], bh[nf][1]);
                }
        }
        __syncthreads();
    }

    // ---- epilogue ----
    const int g = lane >> 2;
    const int t = lane & 3;
#pragma unroll
    for (int mf = 0; mf < 4; ++mf) {
#pragma unroll
        for (int nf = 0; nf < 4; ++nf) {
            int row0 = bm + wm + mf * 16 + g;
            int col  = bn + wn + nf * 8 + 2 * t;
            float v0 = acc[mf][nf][0], v1 = acc[mf][nf][1];
            float v2 = acc[mf][nf][2], v3 = acc[mf][nf][3];
            if (Cin) {
                const float2 i0 = *reinterpret_cast<const float2*>(Cin + (long long)row0 * ldcin + col);
                const float2 i1 = *reinterpret_cast<const float2*>(Cin + (long long)(row0 + 8) * ldcin + col);
                v0 += i0.x; v1 += i0.y; v2 += i1.x; v3 += i1.y;
            }
            *reinterpret_cast<float2*>(C + (long long)row0 * ldc + col)       = make_float2(v0, v1);
            *reinterpret_cast<float2*>(C + (long long)(row0 + 8) * ldc + col) = make_float2(v2, v3);
        }
    }
}

// ---------------- split fp32 -> bf16 hi/lo (with column extraction) --------
__global__ void split_cols(const float* __restrict__ src, int srcld,
                           __nv_bfloat16* __restrict__ hi, __nv_bfloat16* __restrict__ lo,
                           long long rows, int cols)
{
    long long total = rows * cols;
    for (long long idx = blockIdx.x * (long long)blockDim.x + threadIdx.x;
         idx < total; idx += (long long)gridDim.x * blockDim.x) {
        long long r = idx / cols;
        int k = (int)(idx - r * cols);
        float v = src[r * srcld + k];
        __nv_bfloat16 h = __float2bfloat16(v);
        hi[idx] = h;
        lo[idx] = __float2bfloat16(v - __bfloat162float(h));
    }
}

// ---------------- transpose 22-col slab -------------------------------------
__global__ void transpose22(const float* __restrict__ W, int ldw, int col0,
                            float* __restrict__ Wt, int N)
{
    int idx = blockIdx.x * blockDim.x + threadIdx.x;
    if (idx >= Cc * N) return;
    int k = idx / N, n = idx - k * N;
    Wt[idx] = W[(long long)n * ldw + col0 + k];
}

// ---------------- Q = bias + fut @ Wt (K=22, fp32) --------------------------
__global__ void qkernel(const float* __restrict__ fut, const float* __restrict__ Wt,
                        const float* __restrict__ bias, float* __restrict__ out,
                        long long ldo, int N)
{
    int n = blockIdx.x * 256 + threadIdx.x;
    int r = blockIdx.y;
    __shared__ float fr[Cc];
    if (threadIdx.x < Cc) fr[threadIdx.x] = fut[(long long)r * Cc + threadIdx.x];
    __syncthreads();
    float s = bias[n];
#pragma unroll
    for (int k = 0; k < Cc; k++) s += fr[k] * Wt[k * N + n];
    out[(long long)r * ldo + n] = s;
}

// ---------------- pointwise LSTM (i,f,g,o), emits fp32 h + bf16 hi/lo ------
__device__ __forceinline__ float sigm(float x) { return 1.f / (1.f + __expf(-x)); }

__global__ void lstm_pw(const float* __restrict__ gates, long long ldg,
                        float* __restrict__ h, float* __restrict__ c,
                        __nv_bfloat16* __restrict__ h_hi, __nv_bfloat16* __restrict__ h_lo,
                        int rows, int nh)
{
    long long total4 = (long long)rows * (nh / 4);
    for (long long q = blockIdx.x * (long long)blockDim.x + threadIdx.x;
         q < total4; q += (long long)gridDim.x * blockDim.x) {
        int r = (int)(q / (nh / 4));
        int j = (int)(q - (long long)r * (nh / 4)) * 4;
        const float* gr = gates + (long long)r * ldg;
        float4 gi = *reinterpret_cast<const float4*>(gr + j);
        float4 gf = *reinterpret_cast<const float4*>(gr + j + nh);
        float4 gg = *reinterpret_cast<const float4*>(gr + j + 2 * nh);
        float4 go = *reinterpret_cast<const float4*>(gr + j + 3 * nh);
        long long base = (long long)r * nh + j;
        float4 cv = *reinterpret_cast<float4*>(c + base);
        float hv[4], cvn[4];
        float ii[4] = {gi.x, gi.y, gi.z, gi.w};
        float ff[4] = {gf.x, gf.y, gf.z, gf.w};
        float g2[4] = {gg.x, gg.y, gg.z, gg.w};
        float oo[4] = {go.x, go.y, go.z, go.w};
        float cc4[4] = {cv.x, cv.y, cv.z, cv.w};
#pragma unroll
        for (int e = 0; e < 4; e++) {
            float cn = sigm(ff[e]) * cc4[e] + sigm(ii[e]) * tanhf(g2[e]);
            cvn[e] = cn;
            hv[e] = sigm(oo[e]) * tanhf(cn);
        }
        *reinterpret_cast<float4*>(c + base) = make_float4(cvn[0], cvn[1], cvn[2], cvn[3]);
        *reinterpret_cast<float4*>(h + base) = make_float4(hv[0], hv[1], hv[2], hv[3]);
#pragma unroll
        for (int e = 0; e < 4; e++) {
            __nv_bfloat16 hb = __float2bfloat16(hv[e]);
            h_hi[base + e] = hb;
            h_lo[base + e] = __float2bfloat16(hv[e] - __bfloat162float(hb));
        }
    }
}

// ---------------- skinny NT GEMM (warp per output), fp32 -------------------
__global__ void skinny_nt(const float* __restrict__ A, long long lda,
                          const float* __restrict__ Bm, long long ldb, int K,
                          float* __restrict__ C, long long ldc,
                          const float* __restrict__ bias, int M, int N)
{
    int w    = (int)((blockIdx.x * (long long)blockDim.x + threadIdx.x) >> 5);
    int lane = threadIdx.x & 31;
    if (w >= M * N) return;
    int m = w / N, n = w - m * N;
    const float* a = A  + (long long)m * lda;
    const float* b = Bm + (long long)n * ldb;
    float s = 0.f;
    for (int k = lane * 4; k < K; k += 128) {
        float4 av = *reinterpret_cast<const float4*>(a + k);
        float4 bv = *reinterpret_cast<const float4*>(b + k);
        s += av.x * bv.x + av.y * bv.y + av.z * bv.z + av.w * bv.w;
    }
#pragma unroll
    for (int off = 16; off; off >>= 1) s += __shfl_down_sync(0xffffffffu, s, off);
    if (lane == 0) C[(long long)m * ldc + n] = s + (bias ? bias[n] : 0.f);
}

// ---------------- small helpers --------------------------------------------
__global__ void vec_add2(const float* __restrict__ a, const float* __restrict__ b,
                         float* __restrict__ o, int n)
{
    int i = blockIdx.x * blockDim.x + threadIdx.x;
    if (i < n) o[i] = a[i] + b[i];
}

__global__ void scatter_fut(const float* __restrict__ fut, float* __restrict__ outdec, int d)
{
    int idx = blockIdx.x * blockDim.x + threadIdx.x;
    if (idx >= Rr * Cc) return;
    int r = idx / Cc, c = idx - r * Cc;
    outdec[((long long)r * Dd + d) * Cc + c] = fut[idx];
}

// ---------------- launch -----------------------------------------------------
extern "C" void kernel_launch(void* const* d_in, const int* in_sizes, int n_in,
                              void* d_out, int out_size)
{
    const float* x       = (const float*)d_in[0];
    const float* dec_Wih = (const float*)d_in[1];
    const float* dec_Whh = (const float*)d_in[2];
    const float* dec_bih = (const float*)d_in[3];
    const float* dec_bhh = (const float*)d_in[4];
    const float* tr_W    = (const float*)d_in[5];
    const float* tr_b    = (const float*)d_in[6];
    const float* enc_Wih = (const float*)d_in[7];
    const float* enc_Whh = (const float*)d_in[8];
    const float* enc_bih = (const float*)d_in[9];
    const float* enc_bhh = (const float*)d_in[10];
    const float* cls_W   = (const float*)d_in[11];
    const float* cls_b   = (const float*)d_in[12];

    float* out     = (float*)d_out;
    float* out_dec = out + (size_t)Bb * Tt * Cc;

    float *dec_h, *dec_c, *gates, *P, *fut, *egates, *eh, *ec, *dbias, *ebias, *Wt_dec, *Wt_enc;
    __nv_bfloat16 *h_hi, *h_lo, *x_hi, *x_lo, *eh_hi, *eh_lo;
    __nv_bfloat16 *Wdec_hi, *Wdec_lo, *Wih_hi, *Wih_lo, *Whh_hi, *Whh_lo;

    cudaGetSymbolAddress((void**)&dec_h,  g_dec_h);
    cudaGetSymbolAddress((void**)&dec_c,  g_dec_c);
    cudaGetSymbolAddress((void**)&gates,  g_gates);
    cudaGetSymbolAddress((void**)&P,      g_P);
    cudaGetSymbolAddress((void**)&fut,    g_fut);
    cudaGetSymbolAddress((void**)&egates, g_egates);
    cudaGetSymbolAddress((void**)&eh,     g_eh);
    cudaGetSymbolAddress((void**)&ec,     g_ec);
    cudaGetSymbolAddress((void**)&dbias,  g_dbias);
    cudaGetSymbolAddress((void**)&ebias,  g_ebias);
    cudaGetSymbolAddress((void**)&Wt_dec, g_Wt_dec);
    cudaGetSymbolAddress((void**)&Wt_enc, g_Wt_enc);
    cudaGetSymbolAddress((void**)&h_hi,   g_h_hi);
    cudaGetSymbolAddress((void**)&h_lo,   g_h_lo);
    cudaGetSymbolAddress((void**)&x_hi,   g_x_hi);
    cudaGetSymbolAddress((void**)&x_lo,   g_x_lo);
    cudaGetSymbolAddress((void**)&eh_hi,  g_eh_hi);
    cudaGetSymbolAddress((void**)&eh_lo,  g_eh_lo);
    cudaGetSymbolAddress((void**)&Wdec_hi, g_Wdec_hi);
    cudaGetSymbolAddress((void**)&Wdec_lo, g_Wdec_lo);
    cudaGetSymbolAddress((void**)&Wih_hi,  g_Wih_hi);
    cudaGetSymbolAddress((void**)&Wih_lo,  g_Wih_lo);
    cudaGetSymbolAddress((void**)&Whh_hi,  g_Whh_hi);
    cudaGetSymbolAddress((void**)&Whh_lo,  g_Whh_lo);

    cudaFuncSetAttribute(gemm_bf16x3, cudaFuncAttributeMaxDynamicSharedMemorySize, 2 * STAGE_B);

    // ---- init (all graph-capturable) ----
    cudaMemcpyAsync(dec_h, x, sizeof(float) * (size_t)Rr * Ff, cudaMemcpyDeviceToDevice, 0);
    cudaMemsetAsync(dec_c, 0, sizeof(float) * (size_t)Rr * Ff, 0);
    cudaMemsetAsync(fut,   0, sizeof(float) * (size_t)Rr * Cc, 0);
    cudaMemsetAsync(eh,    0, sizeof(float) * (size_t)Bb * Hh, 0);
    cudaMemsetAsync(ec,    0, sizeof(float) * (size_t)Bb * Hh, 0);
    cudaMemsetAsync(eh_hi, 0, sizeof(__nv_bfloat16) * (size_t)Bb * Hh, 0);
    cudaMemsetAsync(eh_lo, 0, sizeof(__nv_bfloat16) * (size_t)Bb * Hh, 0);

    vec_add2<<<(G4f + 255) / 256, 256>>>(dec_bih, dec_bhh, dbias, G4f);
    vec_add2<<<(G4h + 255) / 256, 256>>>(enc_bih, enc_bhh, ebias, G4h);
    transpose22<<<(Cc * G4f + 255) / 256, 256>>>(dec_Wih, Cc, 0, Wt_dec, G4f);
    transpose22<<<(Cc * G4h + 255) / 256, 256>>>(enc_Wih, Ff + Cc, Ff, Wt_enc, G4h);

    {
        int blocks = 4096;
        split_cols<<<blocks, 256>>>(x, Ff, x_hi, x_lo, (long long)Rr, Ff);
        split_cols<<<blocks, 256>>>(x, Ff, h_hi, h_lo, (long long)Rr, Ff);
        split_cols<<<blocks, 256>>>(dec_Whh, Ff, Wdec_hi, Wdec_lo, (long long)G4f, Ff);
        split_cols<<<blocks, 256>>>(enc_Whh, Hh, Whh_hi, Whh_lo, (long long)G4h, Hh);
        split_cols<<<blocks, 256>>>(enc_Wih, Ff + Cc, Wih_hi, Wih_lo, (long long)G4h, Ff);
    }

    // ---- Phase 1: 8 batched decoder steps over R=8192 rows ----
    for (int d = 0; d < Dd; d++) {
        qkernel<<<dim3(G4f / 256, Rr), 256>>>(fut, Wt_dec, dbias, gates, (long long)G4f, G4f);
        gemm_bf16x3<<<dim3(G4f / GBN, Rr / GBM), 256, 2 * STAGE_B>>>(
            h_hi, h_lo, Ff, Wdec_hi, Wdec_lo, Ff, Ff,
            gates, (long long)G4f, gates, (long long)G4f, Rr, G4f);
        long long tot4 = (long long)Rr * Ff / 4;
        lstm_pw<<<(unsigned)((tot4 + 255) / 256), 256>>>(gates, (long long)G4f,
                                                         dec_h, dec_c, h_hi, h_lo, Rr, Ff);
        long long warps = (long long)Rr * Cc;
        skinny_nt<<<(unsigned)((warps * 32 + 255) / 256), 256>>>(dec_h, Ff, tr_W, Ff, Ff,
                                                                 fut, Cc, tr_b, Rr, Cc);
        scatter_fut<<<(Rr * Cc + 255) / 256, 256>>>(fut, out_dec, d);
    }

    // ---- Phase 2: P = [x | fut] @ enc_Wih^T + ebias ----
    qkernel<<<dim3(G4h / 256, Rr), 256>>>(fut, Wt_enc, ebias, P, (long long)G4h, G4h);
    gemm_bf16x3<<<dim3(G4h / GBN, Rr / GBM), 256, 2 * STAGE_B>>>(
        x_hi, x_lo, Ff, Wih_hi, Wih_lo, Ff, Ff,
        P, (long long)G4h, P, (long long)G4h, Rr, G4h);

    // ---- Phase 3: sequential encoder over T=64 ----
    for (int t = 0; t < Tt; t++) {
        gemm_bf16x3<<<dim3(G4h / GBN, Bb / GBM), 256, 2 * STAGE_B>>>(
            eh_hi, eh_lo, Hh, Whh_hi, Whh_lo, Hh, Hh,
            egates, (long long)G4h,
            P + (long long)t * G4h, (long long)Tt * G4h, Bb, G4h);
        long long tot4 = (long long)Bb * Hh / 4;
        lstm_pw<<<(unsigned)((tot4 + 255) / 256), 256>>>(egates, (long long)G4h,
                                                         eh, ec, eh_hi, eh_lo, Bb, Hh);
        long long warps = (long long)Bb * Cc;
        skinny_nt<<<(unsigned)((warps * 32 + 255) / 256), 256>>>(eh, Hh, cls_W, Hh, Hh,
                                                                 out + (long long)t * Cc,
                                                                 (long long)Tt * Cc, cls_b,
                                                                 Bb, Cc);
    }
}

// round 4
// speedup vs baseline: 2.6735x; 1.0028x over previous
#include <cuda_runtime.h>
#include <cuda_bf16.h>
#include <cstdint>
#include <stdint.h>
#include <math.h>

// Problem constants
#define Bb   128
#define Tt   64
#define Ff   2048
#define Hh   2048
#define Cc   22
#define Dd   8
#define Rr   (Bb*Tt)      // 8192
#define G4f  (4*Ff)       // 8192
#define G4h  (4*Hh)       // 8192

// ---------------- scratch (device globals) ---------------------------------
static __device__ float g_dec_h[(size_t)Rr * Ff];
static __device__ float g_dec_c[(size_t)Rr * Ff];
static __device__ float g_gates[(size_t)Rr * G4f];      // 256 MB
static __device__ float g_P    [(size_t)Rr * G4h];      // 256 MB
static __device__ float g_fut  [(size_t)Rr * Cc];
static __device__ float g_egates[(size_t)Bb * G4h];
static __device__ float g_eh   [(size_t)Bb * Hh];
static __device__ float g_ec   [(size_t)Bb * Hh];
static __device__ float g_dbias[G4f];
static __device__ float g_ebias[G4h];
static __device__ float g_Wt_dec[Cc * G4f];             // dec_Wih transposed [22,8192]
static __device__ float g_Wt_enc[Cc * G4h];             // enc_Wih cols 2048..2069 transposed

static __device__ __nv_bfloat16 g_h_hi [(size_t)Rr * Ff],  g_h_lo [(size_t)Rr * Ff];
static __device__ __nv_bfloat16 g_x_hi [(size_t)Rr * Ff],  g_x_lo [(size_t)Rr * Ff];
static __device__ __nv_bfloat16 g_eh_hi[(size_t)Bb * Hh],  g_eh_lo[(size_t)Bb * Hh];
static __device__ __nv_bfloat16 g_Wdec_hi[(size_t)G4f * Ff], g_Wdec_lo[(size_t)G4f * Ff];
static __device__ __nv_bfloat16 g_Wih_hi [(size_t)G4h * Ff], g_Wih_lo [(size_t)G4h * Ff];
static __device__ __nv_bfloat16 g_Whh_hi [(size_t)G4h * Hh], g_Whh_lo [(size_t)G4h * Hh];

// ---------------- PTX helpers ----------------------------------------------
__device__ __forceinline__ void mma_bf16(float* c,
                                         unsigned a0, unsigned a1, unsigned a2, unsigned a3,
                                         unsigned b0, unsigned b1)
{
    asm volatile(
        "mma.sync.aligned.m16n8k16.row.col.f32.bf16.bf16.f32 "
        "{%0,%1,%2,%3}, {%4,%5,%6,%7}, {%8,%9}, {%0,%1,%2,%3};\n"
        : "+f"(c[0]), "+f"(c[1]), "+f"(c[2]), "+f"(c[3])
        : "r"(a0), "r"(a1), "r"(a2), "r"(a3), "r"(b0), "r"(b1));
}
__device__ __forceinline__ void ldsm4(unsigned* r, unsigned addr)
{
    asm volatile("ldmatrix.sync.aligned.m8n8.x4.shared.b16 {%0,%1,%2,%3}, [%4];\n"
                 : "=r"(r[0]), "=r"(r[1]), "=r"(r[2]), "=r"(r[3]) : "r"(addr));
}
__device__ __forceinline__ void ldsm2(unsigned* r, unsigned addr)
{
    asm volatile("ldmatrix.sync.aligned.m8n8.x2.shared.b16 {%0,%1}, [%2];\n"
                 : "=r"(r[0]), "=r"(r[1]) : "r"(addr));
}
__device__ __forceinline__ void cp16(unsigned saddr, const void* g)
{
    asm volatile("cp.async.cg.shared.global [%0], [%1], 16;\n" :: "r"(saddr), "l"(g));
}

// ---------------- bf16x3 tensor-core GEMM ----------------------------------
// C[M,N] = (Ahi+Alo)[M,K] * (Bhi+Blo)[N,K]^T (+ Cin)   [drops lo*lo term]
// M % 128 == 0, N % 128 == 0, K % 32 == 0.  256 threads, warp tile 64x32.
#define GBM 128
#define GBN 128
#define GBK 32
#define SLD 40                         // 32 + 8 pad (bf16 elems)
#define TILE_E (GBM * SLD)             // elems per tile
#define STAGE_E (4 * TILE_E)           // Ahi,Alo,Bhi,Blo
#define OFF_AL (TILE_E * 2)            // byte offsets within stage
#define OFF_BH (2 * TILE_E * 2)
#define OFF_BL (3 * TILE_E * 2)
#define STAGE_B (STAGE_E * 2)

extern __shared__ __nv_bfloat16 smem_[];

__global__ void __launch_bounds__(256, 1)
gemm_bf16x3(const __nv_bfloat16* __restrict__ Ah, const __nv_bfloat16* __restrict__ Al, int lda,
            const __nv_bfloat16* __restrict__ Bh, const __nv_bfloat16* __restrict__ Bl, int ldb,
            int K,
            float* __restrict__ C, long long ldc,
            const float* __restrict__ Cin, long long ldcin,
            int M, int N)
{
    const int bm = blockIdx.y * GBM;
    const int bn = blockIdx.x * GBN;
    const int tid = threadIdx.x;
    const int warp = tid >> 5;
    const int lane = tid & 31;
    const int wm = (warp >> 2) * 64;   // 0 or 64
    const int wn = (warp & 3) * 32;    // 0,32,64,96

    const unsigned sbase = (unsigned)__cvta_generic_to_shared(smem_);

    float acc[4][4][4];
#pragma unroll
    for (int i = 0; i < 4; i++)
#pragma unroll
        for (int j = 0; j < 4; j++)
#pragma unroll
            for (int e = 0; e < 4; e++) acc[i][j][e] = 0.f;

    const int iters = K / GBK;

    // ---- stage loader ----
    auto load_stage = [&](int st, int k0) {
        unsigned so = sbase + st * STAGE_B;
#pragma unroll
        for (int a = 0; a < 2; ++a) {
            int ch = tid + a * 256;            // 0..511
            int row = ch >> 2;
            int kc = (ch & 3) * 8;             // bf16 elems
            unsigned sa = so + (unsigned)(row * SLD + kc) * 2;
            const __nv_bfloat16* ga = Ah + (size_t)(bm + row) * lda + k0 + kc;
            const __nv_bfloat16* gl = Al + (size_t)(bm + row) * lda + k0 + kc;
            const __nv_bfloat16* gb = Bh + (size_t)(bn + row) * ldb + k0 + kc;
            const __nv_bfloat16* gc = Bl + (size_t)(bn + row) * ldb + k0 + kc;
            cp16(sa, ga);
            cp16(sa + OFF_AL, gl);
            cp16(sa + OFF_BH, gb);
            cp16(sa + OFF_BL, gc);
        }
        asm volatile("cp.async.commit_group;\n");
    };

    load_stage(0, 0);

    for (int it = 0; it < iters; ++it) {
        if (it + 1 < iters) {
            load_stage((it + 1) & 1, (it + 1) * GBK);
            asm volatile("cp.async.wait_group 1;\n");
        } else {
            asm volatile("cp.async.wait_group 0;\n");
        }
        __syncthreads();

        unsigned so = sbase + (it & 1) * STAGE_B;
#pragma unroll
        for (int ks = 0; ks < 2; ++ks) {
            unsigned ah[4][4], al[4][4], bh[4][2], bl[4][2];
            const int kb = ks * 16;
            const int arow = wm + (lane & 15);
            const int akb  = kb + ((lane & 16) ? 8 : 0);
#pragma unroll
            for (int mf = 0; mf < 4; ++mf) {
                unsigned ad = so + (unsigned)((arow + mf * 16) * SLD + akb) * 2;
                ldsm4(ah[mf], ad);
                ldsm4(al[mf], ad + OFF_AL);
            }
            const int brow = wn + (lane & 7);
            const int bkb  = kb + ((lane & 8) ? 8 : 0);
#pragma unroll
            for (int nf = 0; nf < 4; ++nf) {
                unsigned bd = so + OFF_BH + (unsigned)((brow + nf * 8) * SLD + bkb) * 2;
                ldsm2(bh[nf], bd);
                ldsm2(bl[nf], bd + (OFF_BL - OFF_BH));
            }
#pragma unroll
            for (int mf = 0; mf < 4; ++mf)
#pragma unroll
                for (int nf = 0; nf < 4; ++nf) {
                    mma_bf16(acc[mf][nf], ah[mf][0], ah[mf][1], ah[mf][2], ah[mf][3],
                             bh[nf][0], bh[nf][1]);
                    mma_bf16(acc[mf][nf], ah[mf][0], ah[mf][1], ah[mf][2], ah[mf][3],
                             bl[nf][0], bl[nf][1]);
                    mma_bf16(acc[mf][nf], al[mf][0], al[mf][1], al[mf][2], al[mf][3],
                             bh[nf][0], bh[nf][1]);
                }
        }
        __syncthreads();
    }

    // ---- epilogue ----
    const int g = lane >> 2;
    const int t = lane & 3;
#pragma unroll
    for (int mf = 0; mf < 4; ++mf) {
#pragma unroll
        for (int nf = 0; nf < 4; ++nf) {
            int row0 = bm + wm + mf * 16 + g;
            int col  = bn + wn + nf * 8 + 2 * t;
            float v0 = acc[mf][nf][0], v1 = acc[mf][nf][1];
            float v2 = acc[mf][nf][2], v3 = acc[mf][nf][3];
            if (Cin) {
                const float2 i0 = *reinterpret_cast<const float2*>(Cin + (long long)row0 * ldcin + col);
                const float2 i1 = *reinterpret_cast<const float2*>(Cin + (long long)(row0 + 8) * ldcin + col);
                v0 += i0.x; v1 += i0.y; v2 += i1.x; v3 += i1.y;
            }
            *reinterpret_cast<float2*>(C + (long long)row0 * ldc + col)       = make_float2(v0, v1);
            *reinterpret_cast<float2*>(C + (long long)(row0 + 8) * ldc + col) = make_float2(v2, v3);
        }
    }
}

// ---------------- split fp32 -> bf16 hi/lo (with column extraction) --------
__global__ void split_cols(const float* __restrict__ src, int srcld,
                           __nv_bfloat16* __restrict__ hi, __nv_bfloat16* __restrict__ lo,
                           long long rows, int cols)
{
    long long total = rows * cols;
    for (long long idx = blockIdx.x * (long long)blockDim.x + threadIdx.x;
         idx < total; idx += (long long)gridDim.x * blockDim.x) {
        long long r = idx / cols;
        int k = (int)(idx - r * cols);
        float v = src[r * srcld + k];
        __nv_bfloat16 h = __float2bfloat16(v);
        hi[idx] = h;
        lo[idx] = __float2bfloat16(v - __bfloat162float(h));
    }
}

// ---------------- transpose 22-col slab -------------------------------------
__global__ void transpose22(const float* __restrict__ W, int ldw, int col0,
                            float* __restrict__ Wt, int N)
{
    int idx = blockIdx.x * blockDim.x + threadIdx.x;
    if (idx >= Cc * N) return;
    int k = idx / N, n = idx - k * N;
    Wt[idx] = W[(long long)n * ldw + col0 + k];
}

// ---------------- Q = bias + fut @ Wt (K=22, fp32) --------------------------
__global__ void qkernel(const float* __restrict__ fut, const float* __restrict__ Wt,
                        const float* __restrict__ bias, float* __restrict__ out,
                        long long ldo, int N)
{
    int n = blockIdx.x * 256 + threadIdx.x;
    int r = blockIdx.y;
    __shared__ float fr[Cc];
    if (threadIdx.x < Cc) fr[threadIdx.x] = fut[(long long)r * Cc + threadIdx.x];
    __syncthreads();
    float s = bias[n];
#pragma unroll
    for (int k = 0; k < Cc; k++) s += fr[k] * Wt[k * N + n];
    out[(long long)r * ldo + n] = s;
}

// ---------------- pointwise LSTM (i,f,g,o), emits fp32 h + bf16 hi/lo ------
__device__ __forceinline__ float sigm(float x) { return 1.f / (1.f + __expf(-x)); }

__global__ void lstm_pw(const float* __restrict__ gates, long long ldg,
                        float* __restrict__ h, float* __restrict__ c,
                        __nv_bfloat16* __restrict__ h_hi, __nv_bfloat16* __restrict__ h_lo,
                        int rows, int nh)
{
    long long total4 = (long long)rows * (nh / 4);
    for (long long q = blockIdx.x * (long long)blockDim.x + threadIdx.x;
         q < total4; q += (long long)gridDim.x * blockDim.x) {
        int r = (int)(q / (nh / 4));
        int j = (int)(q - (long long)r * (nh / 4)) * 4;
        const float* gr = gates + (long long)r * ldg;
        float4 gi = *reinterpret_cast<const float4*>(gr + j);
        float4 gf = *reinterpret_cast<const float4*>(gr + j + nh);
        float4 gg = *reinterpret_cast<const float4*>(gr + j + 2 * nh);
        float4 go = *reinterpret_cast<const float4*>(gr + j + 3 * nh);
        long long base = (long long)r * nh + j;
        float4 cv = *reinterpret_cast<float4*>(c + base);
        float hv[4], cvn[4];
        float ii[4] = {gi.x, gi.y, gi.z, gi.w};
        float ff[4] = {gf.x, gf.y, gf.z, gf.w};
        float g2[4] = {gg.x, gg.y, gg.z, gg.w};
        float oo[4] = {go.x, go.y, go.z, go.w};
        float cc4[4] = {cv.x, cv.y, cv.z, cv.w};
#pragma unroll
        for (int e = 0; e < 4; e++) {
            float cn = sigm(ff[e]) * cc4[e] + sigm(ii[e]) * tanhf(g2[e]);
            cvn[e] = cn;
            hv[e] = sigm(oo[e]) * tanhf(cn);
        }
        *reinterpret_cast<float4*>(c + base) = make_float4(cvn[0], cvn[1], cvn[2], cvn[3]);
        *reinterpret_cast<float4*>(h + base) = make_float4(hv[0], hv[1], hv[2], hv[3]);
#pragma unroll
        for (int e = 0; e < 4; e++) {
            __nv_bfloat16 hb = __float2bfloat16(hv[e]);
            h_hi[base + e] = hb;
            h_lo[base + e] = __float2bfloat16(hv[e] - __bfloat162float(hb));
        }
    }
}

// ---------------- skinny NT GEMM (warp per output), fp32 -------------------
__global__ void skinny_nt(const float* __restrict__ A, long long lda,
                          const float* __restrict__ Bm, long long ldb, int K,
                          float* __restrict__ C, long long ldc,
                          const float* __restrict__ bias, int M, int N)
{
    int w    = (int)((blockIdx.x * (long long)blockDim.x + threadIdx.x) >> 5);
    int lane = threadIdx.x & 31;
    if (w >= M * N) return;
    int m = w / N, n = w - m * N;
    const float* a = A  + (long long)m * lda;
    const float* b = Bm + (long long)n * ldb;
    float s = 0.f;
    for (int k = lane * 4; k < K; k += 128) {
        float4 av = *reinterpret_cast<const float4*>(a + k);
        float4 bv = *reinterpret_cast<const float4*>(b + k);
        s += av.x * bv.x + av.y * bv.y + av.z * bv.z + av.w * bv.w;
    }
#pragma unroll
    for (int off = 16; off; off >>= 1) s += __shfl_down_sync(0xffffffffu, s, off);
    if (lane == 0) C[(long long)m * ldc + n] = s + (bias ? bias[n] : 0.f);
}

// ---------------- small helpers --------------------------------------------
__global__ void vec_add2(const float* __restrict__ a, const float* __restrict__ b,
                         float* __restrict__ o, int n)
{
    int i = blockIdx.x * blockDim.x + threadIdx.x;
    if (i < n) o[i] = a[i] + b[i];
}

__global__ void scatter_fut(const float* __restrict__ fut, float* __restrict__ outdec, int d)
{
    int idx = blockIdx.x * blockDim.x + threadIdx.x;
    if (idx >= Rr * Cc) return;
    int r = idx / Cc, c = idx - r * Cc;
    outdec[((long long)r * Dd + d) * Cc + c] = fut[idx];
}

// ---------------- launch -----------------------------------------------------
extern "C" void kernel_launch(void* const* d_in, const int* in_sizes, int n_in,
                              void* d_out, int out_size)
{
    const float* x       = (const float*)d_in[0];
    const float* dec_Wih = (const float*)d_in[1];
    const float* dec_Whh = (const float*)d_in[2];
    const float* dec_bih = (const float*)d_in[3];
    const float* dec_bhh = (const float*)d_in[4];
    const float* tr_W    = (const float*)d_in[5];
    const float* tr_b    = (const float*)d_in[6];
    const float* enc_Wih = (const float*)d_in[7];
    const float* enc_Whh = (const float*)d_in[8];
    const float* enc_bih = (const float*)d_in[9];
    const float* enc_bhh = (const float*)d_in[10];
    const float* cls_W   = (const float*)d_in[11];
    const float* cls_b   = (const float*)d_in[12];

    float* out     = (float*)d_out;
    float* out_dec = out + (size_t)Bb * Tt * Cc;

    float *dec_h, *dec_c, *gates, *P, *fut, *egates, *eh, *ec, *dbias, *ebias, *Wt_dec, *Wt_enc;
    __nv_bfloat16 *h_hi, *h_lo, *x_hi, *x_lo, *eh_hi, *eh_lo;
    __nv_bfloat16 *Wdec_hi, *Wdec_lo, *Wih_hi, *Wih_lo, *Whh_hi, *Whh_lo;

    cudaGetSymbolAddress((void**)&dec_h,  g_dec_h);
    cudaGetSymbolAddress((void**)&dec_c,  g_dec_c);
    cudaGetSymbolAddress((void**)&gates,  g_gates);
    cudaGetSymbolAddress((void**)&P,      g_P);
    cudaGetSymbolAddress((void**)&fut,    g_fut);
    cudaGetSymbolAddress((void**)&egates, g_egates);
    cudaGetSymbolAddress((void**)&eh,     g_eh);
    cudaGetSymbolAddress((void**)&ec,     g_ec);
    cudaGetSymbolAddress((void**)&dbias,  g_dbias);
    cudaGetSymbolAddress((void**)&ebias,  g_ebias);
    cudaGetSymbolAddress((void**)&Wt_dec, g_Wt_dec);
    cudaGetSymbolAddress((void**)&Wt_enc, g_Wt_enc);
    cudaGetSymbolAddress((void**)&h_hi,   g_h_hi);
    cudaGetSymbolAddress((void**)&h_lo,   g_h_lo);
    cudaGetSymbolAddress((void**)&x_hi,   g_x_hi);
    cudaGetSymbolAddress((void**)&x_lo,   g_x_lo);
    cudaGetSymbolAddress((void**)&eh_hi,  g_eh_hi);
    cudaGetSymbolAddress((void**)&eh_lo,  g_eh_lo);
    cudaGetSymbolAddress((void**)&Wdec_hi, g_Wdec_hi);
    cudaGetSymbolAddress((void**)&Wdec_lo, g_Wdec_lo);
    cudaGetSymbolAddress((void**)&Wih_hi,  g_Wih_hi);
    cudaGetSymbolAddress((void**)&Wih_lo,  g_Wih_lo);
    cudaGetSymbolAddress((void**)&Whh_hi,  g_Whh_hi);
    cudaGetSymbolAddress((void**)&Whh_lo,  g_Whh_lo);

    cudaFuncSetAttribute(gemm_bf16x3, cudaFuncAttributeMaxDynamicSharedMemorySize, 2 * STAGE_B);

    // ---- init (all graph-capturable) ----
    cudaMemcpyAsync(dec_h, x, sizeof(float) * (size_t)Rr * Ff, cudaMemcpyDeviceToDevice, 0);
    cudaMemsetAsync(dec_c, 0, sizeof(float) * (size_t)Rr * Ff, 0);
    cudaMemsetAsync(fut,   0, sizeof(float) * (size_t)Rr * Cc, 0);
    cudaMemsetAsync(eh,    0, sizeof(float) * (size_t)Bb * Hh, 0);
    cudaMemsetAsync(ec,    0, sizeof(float) * (size_t)Bb * Hh, 0);
    cudaMemsetAsync(eh_hi, 0, sizeof(__nv_bfloat16) * (size_t)Bb * Hh, 0);
    cudaMemsetAsync(eh_lo, 0, sizeof(__nv_bfloat16) * (size_t)Bb * Hh, 0);

    vec_add2<<<(G4f + 255) / 256, 256>>>(dec_bih, dec_bhh, dbias, G4f);
    vec_add2<<<(G4h + 255) / 256, 256>>>(enc_bih, enc_bhh, ebias, G4h);
    transpose22<<<(Cc * G4f + 255) / 256, 256>>>(dec_Wih, Cc, 0, Wt_dec, G4f);
    transpose22<<<(Cc * G4h + 255) / 256, 256>>>(enc_Wih, Ff + Cc, Ff, Wt_enc, G4h);

    {
        int blocks = 4096;
        split_cols<<<blocks, 256>>>(x, Ff, x_hi, x_lo, (long long)Rr, Ff);
        split_cols<<<blocks, 256>>>(x, Ff, h_hi, h_lo, (long long)Rr, Ff);
        split_cols<<<blocks, 256>>>(dec_Whh, Ff, Wdec_hi, Wdec_lo, (long long)G4f, Ff);
        split_cols<<<blocks, 256>>>(enc_Whh, Hh, Whh_hi, Whh_lo, (long long)G4h, Hh);
        split_cols<<<blocks, 256>>>(enc_Wih, Ff + Cc, Wih_hi, Wih_lo, (long long)G4h, Ff);
    }

    // ---- Phase 1: 8 batched decoder steps over R=8192 rows ----
    for (int d = 0; d < Dd; d++) {
        qkernel<<<dim3(G4f / 256, Rr), 256>>>(fut, Wt_dec, dbias, gates, (long long)G4f, G4f);
        gemm_bf16x3<<<dim3(G4f / GBN, Rr / GBM), 256, 2 * STAGE_B>>>(
            h_hi, h_lo, Ff, Wdec_hi, Wdec_lo, Ff, Ff,
            gates, (long long)G4f, gates, (long long)G4f, Rr, G4f);
        long long tot4 = (long long)Rr * Ff / 4;
        lstm_pw<<<(unsigned)((tot4 + 255) / 256), 256>>>(gates, (long long)G4f,
                                                         dec_h, dec_c, h_hi, h_lo, Rr, Ff);
        long long warps = (long long)Rr * Cc;
        skinny_nt<<<(unsigned)((warps * 32 + 255) / 256), 256>>>(dec_h, Ff, tr_W, Ff, Ff,
                                                                 fut, Cc, tr_b, Rr, Cc);
        scatter_fut<<<(Rr * Cc + 255) / 256, 256>>>(fut, out_dec, d);
    }

    // ---- Phase 2: P = [x | fut] @ enc_Wih^T + ebias ----
    qkernel<<<dim3(G4h / 256, Rr), 256>>>(fut, Wt_enc, ebias, P, (long long)G4h, G4h);
    gemm_bf16x3<<<dim3(G4h / GBN, Rr / GBM), 256, 2 * STAGE_B>>>(
        x_hi, x_lo, Ff, Wih_hi, Wih_lo, Ff, Ff,
        P, (long long)G4h, P, (long long)G4h, Rr, G4h);

    // ---- Phase 3: sequential encoder over T=64 ----
    for (int t = 0; t < Tt; t++) {
        gemm_bf16x3<<<dim3(G4h / GBN, Bb / GBM), 256, 2 * STAGE_B>>>(
            eh_hi, eh_lo, Hh, Whh_hi, Whh_lo, Hh, Hh,
            egates, (long long)G4h,
            P + (long long)t * G4h, (long long)Tt * G4h, Bb, G4h);
        long long tot4 = (long long)Bb * Hh / 4;
        lstm_pw<<<(unsigned)((tot4 + 255) / 256), 256>>>(egates, (long long)G4h,
                                                         eh, ec, eh_hi, eh_lo, Bb, Hh);
        long long warps = (long long)Bb * Cc;
        skinny_nt<<<(unsigned)((warps * 32 + 255) / 256), 256>>>(eh, Hh, cls_W, Hh, Hh,
                                                                 out + (long long)t * Cc,
                                                                 (long long)Tt * Cc, cls_b,
                                                                 Bb, Cc);
    }
}